// round 12
// baseline (speedup 1.0000x reference)
#include <cuda_runtime.h>
#include <cuda_fp16.h>
#include <cstdint>

// GraphSAGE 2-layer.
//   L1: agg1 = segmean(x) [64]; h = relu([agg1|x] @ [W1l;W1r] + b1) [128]
//   L2: t = h@W2l [64]; hr = h@W2r + b2 [64]; out = segmean(t) + hr
// GEMMs: mma.sync m16n8k16 fp16, A split hi/lo (2 passes), B hi-only, fp32 accum.
// Gathers read fp16 feature copies (x_h, t_h) to halve L2 traffic.

#define MAXN 100000
#define MAXE 1600000

__device__ int     g_is64;
__device__ int     g_src[MAXE];
__device__ int     g_dst[MAXE];
__device__ int     g_cnt[MAXN];
__device__ int     g_row[MAXN + 1];
__device__ int     g_next[MAXN];
__device__ int     g_col[MAXE];
__device__ int     g_bs[1024];
__device__ int     g_bo[1024];
__device__ float   g_agg[MAXN * 64];
__device__ float   g_h[MAXN * 128];
__device__ __half2 g_xh[MAXN * 32];
__device__ __half2 g_th[MAXN * 32];
// fp16-hi weight tile for current layer: [n:128][kw:64 words]
__device__ uint32_t g_wb[128 * 64];

// ---------------- init: zero counts + edge dtype detect ----------------

__global__ void k_init(const int* __restrict__ ei32, int n) {
    int i = blockIdx.x * blockDim.x + threadIdx.x;
    if (i < n) g_cnt[i] = 0;
    if (i == 0) {
        int s = 0;
        #pragma unroll
        for (int j = 0; j < 64; j++) s |= ei32[2 * j + 1];
        g_is64 = (s == 0) ? 1 : 0;
    }
}

// ---------------- x -> fp16 copy ----------------

__global__ void k_xconv(const float* __restrict__ x, int n) {
    int i = blockIdx.x * blockDim.x + threadIdx.x;
    if (i < n * 32) {
        float2 v = ((const float2*)x)[i];
        g_xh[i] = __floats2half2_rn(v.x, v.y);
    }
}

// ---------------- CSR build ----------------

__global__ void k_hist(const void* __restrict__ ei, int E, int n) {
    int e = blockIdx.x * blockDim.x + threadIdx.x;
    if (e >= E) return;
    int s, d;
    if (g_is64) {
        const long long* p = (const long long*)ei;
        s = (int)p[e];
        d = (int)p[E + e];
    } else {
        const int* p = (const int*)ei;
        s = p[e];
        d = p[E + e];
    }
    s = min(max(s, 0), n - 1);
    d = min(max(d, 0), n - 1);
    g_src[e] = s;
    g_dst[e] = d;
    atomicAdd(&g_cnt[d], 1);
}

__global__ void k_scanA(int n) {
    __shared__ int s[1024];
    int i = blockIdx.x * 1024 + threadIdx.x;
    int v = (i < n) ? g_cnt[i] : 0;
    s[threadIdx.x] = v;
    __syncthreads();
    for (int off = 1; off < 1024; off <<= 1) {
        int t = (threadIdx.x >= off) ? s[threadIdx.x - off] : 0;
        __syncthreads();
        s[threadIdx.x] += t;
        __syncthreads();
    }
    if (i < n) g_row[i] = s[threadIdx.x] - v;
    if (threadIdx.x == 1023) g_bs[blockIdx.x] = s[1023];
}

__global__ void k_scanB(int nb) {
    __shared__ int s[1024];
    int v = (threadIdx.x < nb) ? g_bs[threadIdx.x] : 0;
    s[threadIdx.x] = v;
    __syncthreads();
    for (int off = 1; off < 1024; off <<= 1) {
        int t = (threadIdx.x >= off) ? s[threadIdx.x - off] : 0;
        __syncthreads();
        s[threadIdx.x] += t;
        __syncthreads();
    }
    g_bo[threadIdx.x] = s[threadIdx.x] - v;
}

__global__ void k_scanC(int n, int E) {
    int i = blockIdx.x * blockDim.x + threadIdx.x;
    if (i < n) {
        int r = g_row[i] + g_bo[i >> 10];
        g_row[i] = r;
        g_next[i] = r;
    }
    if (i == 0) g_row[n] = E;
}

__global__ void k_fill(int E) {
    int e = blockIdx.x * blockDim.x + threadIdx.x;
    if (e < E) {
        int p = atomicAdd(&g_next[g_dst[e]], 1);
        g_col[p] = g_src[e];
    }
}

// ---------------- segment mean over fp16 features (64 feats, 1 warp/node) ----------------

__global__ void k_aggmean(const __half2* __restrict__ src, float* __restrict__ dstArr, int n) {
    int w = (blockIdx.x * blockDim.x + threadIdx.x) >> 5;
    int lane = threadIdx.x & 31;
    if (w >= n) return;
    int beg = g_row[w], end = g_row[w + 1];
    float sx = 0.f, sy = 0.f;
    int j = beg;
    for (; j + 4 <= end; j += 4) {
        int c0 = __ldg(&g_col[j]);
        int c1 = __ldg(&g_col[j + 1]);
        int c2 = __ldg(&g_col[j + 2]);
        int c3 = __ldg(&g_col[j + 3]);
        float2 v0 = __half22float2(__ldg(&src[c0 * 32 + lane]));
        float2 v1 = __half22float2(__ldg(&src[c1 * 32 + lane]));
        float2 v2 = __half22float2(__ldg(&src[c2 * 32 + lane]));
        float2 v3 = __half22float2(__ldg(&src[c3 * 32 + lane]));
        sx += v0.x + v1.x + v2.x + v3.x;
        sy += v0.y + v1.y + v2.y + v3.y;
    }
    for (; j < end; j++) {
        int c = __ldg(&g_col[j]);
        float2 v = __half22float2(__ldg(&src[c * 32 + lane]));
        sx += v.x;
        sy += v.y;
    }
    int deg = end - beg;
    float inv = 1.0f / (float)(deg > 0 ? deg : 1);
    ((float2*)dstArr)[w * 32 + lane] = make_float2(sx * inv, sy * inv);
}

__global__ void k_aggmean_add(const __half2* __restrict__ src, float* __restrict__ out, int n) {
    int w = (blockIdx.x * blockDim.x + threadIdx.x) >> 5;
    int lane = threadIdx.x & 31;
    if (w >= n) return;
    int beg = g_row[w], end = g_row[w + 1];
    float sx = 0.f, sy = 0.f;
    int j = beg;
    for (; j + 4 <= end; j += 4) {
        int c0 = __ldg(&g_col[j]);
        int c1 = __ldg(&g_col[j + 1]);
        int c2 = __ldg(&g_col[j + 2]);
        int c3 = __ldg(&g_col[j + 3]);
        float2 v0 = __half22float2(__ldg(&src[c0 * 32 + lane]));
        float2 v1 = __half22float2(__ldg(&src[c1 * 32 + lane]));
        float2 v2 = __half22float2(__ldg(&src[c2 * 32 + lane]));
        float2 v3 = __half22float2(__ldg(&src[c3 * 32 + lane]));
        sx += v0.x + v1.x + v2.x + v3.x;
        sy += v0.y + v1.y + v2.y + v3.y;
    }
    for (; j < end; j++) {
        int c = __ldg(&g_col[j]);
        float2 v = __half22float2(__ldg(&src[c * 32 + lane]));
        sx += v.x;
        sy += v.y;
    }
    int deg = end - beg;
    float inv = 1.0f / (float)(deg > 0 ? deg : 1);
    float2* o2 = (float2*)out;
    float2 cur = o2[w * 32 + lane];
    cur.x += sx * inv;
    cur.y += sy * inv;
    o2[w * 32 + lane] = cur;
}

// ---------------- weight precompute: g_wb = fp16-hi of B[n][k] ----------------

__global__ void k_wconv(int mode, const float* __restrict__ Wl, const float* __restrict__ Wr) {
    int i = blockIdx.x * blockDim.x + threadIdx.x;
    if (i >= 128 * 64) return;
    int nn = i >> 6;
    int k = (i & 63) * 2;
    float w0, w1;
    if (mode == 0) {
        w0 = (k < 64) ? Wl[k * 128 + nn] : Wr[(k - 64) * 128 + nn];
        w1 = (k + 1 < 64) ? Wl[(k + 1) * 128 + nn] : Wr[(k + 1 - 64) * 128 + nn];
    } else {
        const float* W = (nn < 64) ? Wl : Wr;
        int c = (nn < 64) ? nn : nn - 64;
        w0 = W[k * 64 + c];
        w1 = W[(k + 1) * 64 + c];
    }
    __half h0 = __float2half_rn(w0);
    __half h1 = __float2half_rn(w1);
    g_wb[i] = (uint32_t)__half_as_ushort(h0) | ((uint32_t)__half_as_ushort(h1) << 16);
}

// ---------------- GEMM: D[128,128] = A @ B^T, fp16 A-hi/lo 2-pass ----------------
// mode 0: A = [agg|x], epilogue h = relu(D + b1)
// mode 1: A = h, epilogue cols<64 -> t_h (fp16), cols>=64 -> out = D + b2

#define KW 68  // row stride in 32-bit words (payload 64 = 128 fp16 k-values)
#define SM_AH 0
#define SM_AL (128 * KW)
#define SM_BH (2 * 128 * KW)
#define SM_BIAS (3 * 128 * KW)
#define SMEM_WORDS (3 * 128 * KW + 128)
#define SMEM_MMA_BYTES (SMEM_WORDS * 4)

__global__ void __launch_bounds__(256, 2)
k_mma(int mode, const float* __restrict__ A0, const float* __restrict__ A1,
      const float* __restrict__ bias, float* __restrict__ O0,
      __half2* __restrict__ Oth, float* __restrict__ O1, int n)
{
    extern __shared__ uint32_t sm4[];
    int tid = threadIdx.x, wid = tid >> 5, lane = tid & 31;
    int row0 = blockIdx.x * 128;

    // ---- A tile: fp32 -> fp16 hi/lo ----
    for (int i = tid; i < 128 * 64; i += 256) {
        int m = i >> 6, kw = i & 63;
        int row = row0 + m;
        float2 v = make_float2(0.f, 0.f);
        if (row < n) {
            if (mode == 0)
                v = (kw < 32) ? __ldg(&((const float2*)A0)[row * 32 + kw])
                              : __ldg(&((const float2*)A1)[row * 32 + (kw - 32)]);
            else
                v = __ldg(&((const float2*)A0)[row * 64 + kw]);
        }
        __half h0 = __float2half_rn(v.x);
        __half h1 = __float2half_rn(v.y);
        __half l0 = __float2half_rn(v.x - __half2float(h0));
        __half l1 = __float2half_rn(v.y - __half2float(h1));
        sm4[SM_AH + m * KW + kw] = (uint32_t)__half_as_ushort(h0) | ((uint32_t)__half_as_ushort(h1) << 16);
        sm4[SM_AL + m * KW + kw] = (uint32_t)__half_as_ushort(l0) | ((uint32_t)__half_as_ushort(l1) << 16);
    }
    // ---- B tile (hi only): coalesced copy ----
    for (int i = tid; i < 128 * 64; i += 256) {
        int nn = i >> 6, kw = i & 63;
        sm4[SM_BH + nn * KW + kw] = g_wb[i];
    }
    if (tid < 128) {
        float bv = 0.f;
        if (mode == 0) bv = __ldg(&bias[tid]);
        else if (tid < 64) bv = __ldg(&bias[tid]);
        ((float*)(sm4 + SM_BIAS))[tid] = bv;
    }
    __syncthreads();

    int warp_m = wid & 3, warp_n = wid >> 2;
    int lr = lane >> 2;  // 0..7
    int lc = lane & 3;   // 0..3

    float acc[2][8][4];
    #pragma unroll
    for (int mt = 0; mt < 2; mt++)
        #pragma unroll
        for (int nt = 0; nt < 8; nt++)
            #pragma unroll
            for (int q = 0; q < 4; q++) acc[mt][nt][q] = 0.f;

    int a_row_in_tile = lane & 15;
    int a_kw_off = (lane >> 4) << 2;
    int b_row_in_grp = (lane & 7) + ((lane >> 4) << 3);
    int b_kw_off = ((lane >> 3) & 1) << 2;

    #pragma unroll 1
    for (int pass = 0; pass < 2; pass++) {
        const uint32_t* Ap = sm4 + ((pass == 0) ? SM_AH : SM_AL);
        const uint32_t* Bp = sm4 + SM_BH;
        #pragma unroll
        for (int ks = 0; ks < 8; ks++) {
            int kwb = ks * 8;
            uint32_t a[2][4];
            #pragma unroll
            for (int mt = 0; mt < 2; mt++) {
                int r = warp_m * 32 + mt * 16 + a_row_in_tile;
                uint32_t addr = (uint32_t)__cvta_generic_to_shared(&Ap[r * KW + kwb + a_kw_off]);
                asm volatile("ldmatrix.sync.aligned.m8n8.x4.shared.b16 {%0,%1,%2,%3}, [%4];"
                             : "=r"(a[mt][0]), "=r"(a[mt][1]), "=r"(a[mt][2]), "=r"(a[mt][3])
                             : "r"(addr));
            }
            uint32_t br[4][4];
            #pragma unroll
            for (int ng = 0; ng < 4; ng++) {
                int nb = warp_n * 64 + ng * 16 + b_row_in_grp;
                uint32_t addr = (uint32_t)__cvta_generic_to_shared(&Bp[nb * KW + kwb + b_kw_off]);
                asm volatile("ldmatrix.sync.aligned.m8n8.x4.shared.b16 {%0,%1,%2,%3}, [%4];"
                             : "=r"(br[ng][0]), "=r"(br[ng][1]), "=r"(br[ng][2]), "=r"(br[ng][3])
                             : "r"(addr));
            }
            #pragma unroll
            for (int ng = 0; ng < 4; ng++) {
                #pragma unroll
                for (int sub = 0; sub < 2; sub++) {
                    int nt = ng * 2 + sub;
                    uint32_t b0 = br[ng][sub * 2], b1 = br[ng][sub * 2 + 1];
                    #pragma unroll
                    for (int mt = 0; mt < 2; mt++) {
                        asm volatile(
                            "mma.sync.aligned.m16n8k16.row.col.f32.f16.f16.f32 "
                            "{%0,%1,%2,%3}, {%4,%5,%6,%7}, {%8,%9}, {%0,%1,%2,%3};"
                            : "+f"(acc[mt][nt][0]), "+f"(acc[mt][nt][1]),
                              "+f"(acc[mt][nt][2]), "+f"(acc[mt][nt][3])
                            : "r"(a[mt][0]), "r"(a[mt][1]), "r"(a[mt][2]), "r"(a[mt][3]),
                              "r"(b0), "r"(b1));
                    }
                }
            }
        }
    }

    // ---- epilogue ----
    const float* sb = (const float*)(sm4 + SM_BIAS);
    #pragma unroll
    for (int mt = 0; mt < 2; mt++) {
        int rbase = row0 + warp_m * 32 + mt * 16 + lr;
        #pragma unroll
        for (int nt = 0; nt < 8; nt++) {
            int col = warp_n * 64 + nt * 8 + lc * 2;
            #pragma unroll
            for (int half = 0; half < 2; half++) {
                int row = rbase + half * 8;
                if (row >= n) continue;
                float v0 = acc[mt][nt][half * 2 + 0];
                float v1 = acc[mt][nt][half * 2 + 1];
                if (mode == 0) {
                    v0 = fmaxf(v0 + sb[col], 0.f);
                    v1 = fmaxf(v1 + sb[col + 1], 0.f);
                    *(float2*)&O0[row * 128 + col] = make_float2(v0, v1);
                } else if (warp_n == 0) {
                    Oth[row * 32 + (col >> 1)] = __floats2half2_rn(v0, v1);
                } else {
                    int cb = col - 64;
                    v0 += sb[cb];
                    v1 += sb[cb + 1];
                    *(float2*)&O1[row * 64 + cb] = make_float2(v0, v1);
                }
            }
        }
    }
}

// ---------------- launch ----------------

extern "C" void kernel_launch(void* const* d_in, const int* in_sizes, int n_in,
                              void* d_out, int out_size) {
    const float* x = (const float*)d_in[0];
    const void* ei = d_in[1];
    const float* W1l = (const float*)d_in[2];
    const float* W1r = (const float*)d_in[3];
    const float* b1 = (const float*)d_in[4];
    const float* W2l = (const float*)d_in[5];
    const float* W2r = (const float*)d_in[6];
    const float* b2 = (const float*)d_in[7];
    float* out = (float*)d_out;

    int n = in_sizes[0] / 64;
    int E = in_sizes[1] / 2;

    float*   agg;  cudaGetSymbolAddress((void**)&agg, g_agg);
    float*   h;    cudaGetSymbolAddress((void**)&h, g_h);
    __half2* xh;   cudaGetSymbolAddress((void**)&xh, g_xh);
    __half2* th;   cudaGetSymbolAddress((void**)&th, g_th);

    cudaFuncSetAttribute(k_mma, cudaFuncAttributeMaxDynamicSharedMemorySize, SMEM_MMA_BYTES);

    int nb = (n + 1023) / 1024;
    int ntile = (n + 127) / 128;

    k_init<<<(n + 255) / 256, 256>>>((const int*)ei, n);
    k_xconv<<<(n * 32 + 255) / 256, 256>>>(x, n);
    k_hist<<<(E + 255) / 256, 256>>>(ei, E, n);
    k_scanA<<<nb, 1024>>>(n);
    k_scanB<<<1, 1024>>>(nb);
    k_scanC<<<(n + 255) / 256, 256>>>(n, E);
    k_fill<<<(E + 255) / 256, 256>>>(E);

    // layer 1
    k_aggmean<<<(n * 32 + 255) / 256, 256>>>(xh, agg, n);
    k_wconv<<<32, 256>>>(0, W1l, W1r);
    k_mma<<<ntile, 256, SMEM_MMA_BYTES>>>(0, agg, x, b1, h, nullptr, nullptr, n);

    // layer 2
    k_wconv<<<32, 256>>>(1, W2l, W2r);
    k_mma<<<ntile, 256, SMEM_MMA_BYTES>>>(1, h, nullptr, b2, nullptr, th, out, n);
    k_aggmean_add<<<(n * 32 + 255) / 256, 256>>>(th, out, n);
}

// round 14
// speedup vs baseline: 1.0883x; 1.0883x over previous
#include <cuda_runtime.h>
#include <cuda_fp16.h>
#include <cstdint>

// GraphSAGE 2-layer.
//   L1: agg1 = segmean(x) [64]; h = relu([agg1|x] @ [W1l;W1r] + b1) [128]
//   L2: t = h@W2l [64]; hr = h@W2r + b2 [64]; out = segmean(t) + hr
// GEMMs: mma.sync m16n8k16 fp16, A split hi/lo (2 passes), B hi-only, fp32 accum.
// Gathers fp32, 8-deep unrolled for MLP.

#define MAXN 100000
#define MAXE 1600000

__device__ int     g_is64;
__device__ int     g_src[MAXE];
__device__ int     g_dst[MAXE];
__device__ int     g_cnt[MAXN];
__device__ int     g_row[MAXN + 1];
__device__ int     g_next[MAXN];
__device__ int     g_col[MAXE];
__device__ int     g_bs[1024];
__device__ int     g_bo[1024];
__device__ float   g_agg[MAXN * 64];
__device__ float   g_h[MAXN * 128];
__device__ float   g_t[MAXN * 64];
// fp16-hi weight tiles, one per layer: [n:128][kw:64 words]
__device__ uint32_t g_wb[2][128 * 64];

// ---------------- init: zero counts + edge dtype detect ----------------

__global__ void k_init(const int* __restrict__ ei32, int n) {
    int i = blockIdx.x * blockDim.x + threadIdx.x;
    if (i < n) g_cnt[i] = 0;
    if (i == 0) {
        int s = 0;
        #pragma unroll
        for (int j = 0; j < 64; j++) s |= ei32[2 * j + 1];
        g_is64 = (s == 0) ? 1 : 0;
    }
}

// ---------------- CSR build ----------------

__global__ void k_hist(const void* __restrict__ ei, int E, int n) {
    int e = blockIdx.x * blockDim.x + threadIdx.x;
    if (e >= E) return;
    int s, d;
    if (g_is64) {
        const long long* p = (const long long*)ei;
        s = (int)p[e];
        d = (int)p[E + e];
    } else {
        const int* p = (const int*)ei;
        s = p[e];
        d = p[E + e];
    }
    s = min(max(s, 0), n - 1);
    d = min(max(d, 0), n - 1);
    g_src[e] = s;
    g_dst[e] = d;
    atomicAdd(&g_cnt[d], 1);
}

__global__ void k_scanA(int n) {
    __shared__ int s[1024];
    int i = blockIdx.x * 1024 + threadIdx.x;
    int v = (i < n) ? g_cnt[i] : 0;
    s[threadIdx.x] = v;
    __syncthreads();
    for (int off = 1; off < 1024; off <<= 1) {
        int t = (threadIdx.x >= off) ? s[threadIdx.x - off] : 0;
        __syncthreads();
        s[threadIdx.x] += t;
        __syncthreads();
    }
    if (i < n) g_row[i] = s[threadIdx.x] - v;
    if (threadIdx.x == 1023) g_bs[blockIdx.x] = s[1023];
}

__global__ void k_scanB(int nb) {
    __shared__ int s[1024];
    int v = (threadIdx.x < nb) ? g_bs[threadIdx.x] : 0;
    s[threadIdx.x] = v;
    __syncthreads();
    for (int off = 1; off < 1024; off <<= 1) {
        int t = (threadIdx.x >= off) ? s[threadIdx.x - off] : 0;
        __syncthreads();
        s[threadIdx.x] += t;
        __syncthreads();
    }
    g_bo[threadIdx.x] = s[threadIdx.x] - v;
}

__global__ void k_scanC(int n, int E) {
    int i = blockIdx.x * blockDim.x + threadIdx.x;
    if (i < n) {
        int r = g_row[i] + g_bo[i >> 10];
        g_row[i] = r;
        g_next[i] = r;
    }
    if (i == 0) g_row[n] = E;
}

__global__ void k_fill(int E) {
    int e = blockIdx.x * blockDim.x + threadIdx.x;
    if (e < E) {
        int p = atomicAdd(&g_next[g_dst[e]], 1);
        g_col[p] = g_src[e];
    }
}

// ---------------- segment mean (64 feats, 1 warp/node, 8-deep MLP) ----------------

__global__ void k_aggmean(const float* __restrict__ src, float* __restrict__ dstArr, int n) {
    int w = (blockIdx.x * blockDim.x + threadIdx.x) >> 5;
    int lane = threadIdx.x & 31;
    if (w >= n) return;
    int beg = g_row[w], end = g_row[w + 1];
    const float2* s2 = (const float2*)src;
    float sx = 0.f, sy = 0.f;
    int j = beg;
    for (; j + 8 <= end; j += 8) {
        int c[8];
        #pragma unroll
        for (int q = 0; q < 8; q++) c[q] = __ldg(&g_col[j + q]);
        float2 v[8];
        #pragma unroll
        for (int q = 0; q < 8; q++) v[q] = __ldg(&s2[c[q] * 32 + lane]);
        #pragma unroll
        for (int q = 0; q < 8; q++) { sx += v[q].x; sy += v[q].y; }
    }
    for (; j + 2 <= end; j += 2) {
        int c0 = __ldg(&g_col[j]);
        int c1 = __ldg(&g_col[j + 1]);
        float2 v0 = __ldg(&s2[c0 * 32 + lane]);
        float2 v1 = __ldg(&s2[c1 * 32 + lane]);
        sx += v0.x + v1.x;
        sy += v0.y + v1.y;
    }
    for (; j < end; j++) {
        int c = __ldg(&g_col[j]);
        float2 v = __ldg(&s2[c * 32 + lane]);
        sx += v.x;
        sy += v.y;
    }
    int deg = end - beg;
    float inv = 1.0f / (float)(deg > 0 ? deg : 1);
    ((float2*)dstArr)[w * 32 + lane] = make_float2(sx * inv, sy * inv);
}

__global__ void k_aggmean_add(const float* __restrict__ src, float* __restrict__ out, int n) {
    int w = (blockIdx.x * blockDim.x + threadIdx.x) >> 5;
    int lane = threadIdx.x & 31;
    if (w >= n) return;
    int beg = g_row[w], end = g_row[w + 1];
    const float2* s2 = (const float2*)src;
    float sx = 0.f, sy = 0.f;
    int j = beg;
    for (; j + 8 <= end; j += 8) {
        int c[8];
        #pragma unroll
        for (int q = 0; q < 8; q++) c[q] = __ldg(&g_col[j + q]);
        float2 v[8];
        #pragma unroll
        for (int q = 0; q < 8; q++) v[q] = __ldg(&s2[c[q] * 32 + lane]);
        #pragma unroll
        for (int q = 0; q < 8; q++) { sx += v[q].x; sy += v[q].y; }
    }
    for (; j + 2 <= end; j += 2) {
        int c0 = __ldg(&g_col[j]);
        int c1 = __ldg(&g_col[j + 1]);
        float2 v0 = __ldg(&s2[c0 * 32 + lane]);
        float2 v1 = __ldg(&s2[c1 * 32 + lane]);
        sx += v0.x + v1.x;
        sy += v0.y + v1.y;
    }
    for (; j < end; j++) {
        int c = __ldg(&g_col[j]);
        float2 v = __ldg(&s2[c * 32 + lane]);
        sx += v.x;
        sy += v.y;
    }
    int deg = end - beg;
    float inv = 1.0f / (float)(deg > 0 ? deg : 1);
    float2* o2 = (float2*)out;
    float2 cur = o2[w * 32 + lane];
    cur.x += sx * inv;
    cur.y += sy * inv;
    o2[w * 32 + lane] = cur;
}

// ---------------- weight precompute: fp16-hi of B[n][k] ----------------

__global__ void k_wconv(int mode, const float* __restrict__ Wl, const float* __restrict__ Wr) {
    int i = blockIdx.x * blockDim.x + threadIdx.x;
    if (i >= 128 * 64) return;
    int nn = i >> 6;
    int k = (i & 63) * 2;
    float w0, w1;
    if (mode == 0) {
        w0 = (k < 64) ? Wl[k * 128 + nn] : Wr[(k - 64) * 128 + nn];
        w1 = (k + 1 < 64) ? Wl[(k + 1) * 128 + nn] : Wr[(k + 1 - 64) * 128 + nn];
    } else {
        const float* W = (nn < 64) ? Wl : Wr;
        int c = (nn < 64) ? nn : nn - 64;
        w0 = W[k * 64 + c];
        w1 = W[(k + 1) * 64 + c];
    }
    __half h0 = __float2half_rn(w0);
    __half h1 = __float2half_rn(w1);
    g_wb[mode][i] = (uint32_t)__half_as_ushort(h0) | ((uint32_t)__half_as_ushort(h1) << 16);
}

// ---------------- GEMM: D[128,128] = A @ B^T, fp16 A-hi/lo 2-pass ----------------
// mode 0: A = [agg|x], epilogue h = relu(D + b1)
// mode 1: A = h, epilogue cols<64 -> t = D, cols>=64 -> out = D + b2

#define KW 68
#define SM_AH 0
#define SM_AL (128 * KW)
#define SM_BH (2 * 128 * KW)
#define SM_BIAS (3 * 128 * KW)
#define SMEM_WORDS (3 * 128 * KW + 128)
#define SMEM_MMA_BYTES (SMEM_WORDS * 4)

__global__ void __launch_bounds__(256, 2)
k_mma(int mode, const float* __restrict__ A0, const float* __restrict__ A1,
      const float* __restrict__ bias, float* __restrict__ O0, float* __restrict__ O1, int n)
{
    extern __shared__ uint32_t sm4[];
    int tid = threadIdx.x, wid = tid >> 5, lane = tid & 31;
    int row0 = blockIdx.x * 128;
    const uint32_t* wb = g_wb[mode];

    for (int i = tid; i < 128 * 64; i += 256) {
        int m = i >> 6, kw = i & 63;
        int row = row0 + m;
        float2 v = make_float2(0.f, 0.f);
        if (row < n) {
            if (mode == 0)
                v = (kw < 32) ? __ldg(&((const float2*)A0)[row * 32 + kw])
                              : __ldg(&((const float2*)A1)[row * 32 + (kw - 32)]);
            else
                v = __ldg(&((const float2*)A0)[row * 64 + kw]);
        }
        __half h0 = __float2half_rn(v.x);
        __half h1 = __float2half_rn(v.y);
        __half l0 = __float2half_rn(v.x - __half2float(h0));
        __half l1 = __float2half_rn(v.y - __half2float(h1));
        sm4[SM_AH + m * KW + kw] = (uint32_t)__half_as_ushort(h0) | ((uint32_t)__half_as_ushort(h1) << 16);
        sm4[SM_AL + m * KW + kw] = (uint32_t)__half_as_ushort(l0) | ((uint32_t)__half_as_ushort(l1) << 16);
    }
    for (int i = tid; i < 128 * 64; i += 256) {
        int nn = i >> 6, kw = i & 63;
        sm4[SM_BH + nn * KW + kw] = wb[i];
    }
    if (tid < 128) {
        float bv = 0.f;
        if (mode == 0) bv = __ldg(&bias[tid]);
        else if (tid < 64) bv = __ldg(&bias[tid]);
        ((float*)(sm4 + SM_BIAS))[tid] = bv;
    }
    __syncthreads();

    int warp_m = wid & 3, warp_n = wid >> 2;
    int lr = lane >> 2;
    int lc = lane & 3;

    float acc[2][8][4];
    #pragma unroll
    for (int mt = 0; mt < 2; mt++)
        #pragma unroll
        for (int nt = 0; nt < 8; nt++)
            #pragma unroll
            for (int q = 0; q < 4; q++) acc[mt][nt][q] = 0.f;

    int a_row_in_tile = lane & 15;
    int a_kw_off = (lane >> 4) << 2;
    int b_row_in_grp = (lane & 7) + ((lane >> 4) << 3);
    int b_kw_off = ((lane >> 3) & 1) << 2;

    #pragma unroll 1
    for (int pass = 0; pass < 2; pass++) {
        const uint32_t* Ap = sm4 + ((pass == 0) ? SM_AH : SM_AL);
        const uint32_t* Bp = sm4 + SM_BH;
        #pragma unroll
        for (int ks = 0; ks < 8; ks++) {
            int kwb = ks * 8;
            uint32_t a[2][4];
            #pragma unroll
            for (int mt = 0; mt < 2; mt++) {
                int r = warp_m * 32 + mt * 16 + a_row_in_tile;
                uint32_t addr = (uint32_t)__cvta_generic_to_shared(&Ap[r * KW + kwb + a_kw_off]);
                asm volatile("ldmatrix.sync.aligned.m8n8.x4.shared.b16 {%0,%1,%2,%3}, [%4];"
                             : "=r"(a[mt][0]), "=r"(a[mt][1]), "=r"(a[mt][2]), "=r"(a[mt][3])
                             : "r"(addr));
            }
            uint32_t br[4][4];
            #pragma unroll
            for (int ng = 0; ng < 4; ng++) {
                int nb = warp_n * 64 + ng * 16 + b_row_in_grp;
                uint32_t addr = (uint32_t)__cvta_generic_to_shared(&Bp[nb * KW + kwb + b_kw_off]);
                asm volatile("ldmatrix.sync.aligned.m8n8.x4.shared.b16 {%0,%1,%2,%3}, [%4];"
                             : "=r"(br[ng][0]), "=r"(br[ng][1]), "=r"(br[ng][2]), "=r"(br[ng][3])
                             : "r"(addr));
            }
            #pragma unroll
            for (int ng = 0; ng < 4; ng++) {
                #pragma unroll
                for (int sub = 0; sub < 2; sub++) {
                    int nt = ng * 2 + sub;
                    uint32_t b0 = br[ng][sub * 2], b1 = br[ng][sub * 2 + 1];
                    #pragma unroll
                    for (int mt = 0; mt < 2; mt++) {
                        asm volatile(
                            "mma.sync.aligned.m16n8k16.row.col.f32.f16.f16.f32 "
                            "{%0,%1,%2,%3}, {%4,%5,%6,%7}, {%8,%9}, {%0,%1,%2,%3};"
                            : "+f"(acc[mt][nt][0]), "+f"(acc[mt][nt][1]),
                              "+f"(acc[mt][nt][2]), "+f"(acc[mt][nt][3])
                            : "r"(a[mt][0]), "r"(a[mt][1]), "r"(a[mt][2]), "r"(a[mt][3]),
                              "r"(b0), "r"(b1));
                    }
                }
            }
        }
    }

    const float* sb = (const float*)(sm4 + SM_BIAS);
    #pragma unroll
    for (int mt = 0; mt < 2; mt++) {
        int rbase = row0 + warp_m * 32 + mt * 16 + lr;
        #pragma unroll
        for (int nt = 0; nt < 8; nt++) {
            int col = warp_n * 64 + nt * 8 + lc * 2;
            #pragma unroll
            for (int half = 0; half < 2; half++) {
                int row = rbase + half * 8;
                if (row >= n) continue;
                float v0 = acc[mt][nt][half * 2 + 0];
                float v1 = acc[mt][nt][half * 2 + 1];
                if (mode == 0) {
                    v0 = fmaxf(v0 + sb[col], 0.f);
                    v1 = fmaxf(v1 + sb[col + 1], 0.f);
                    *(float2*)&O0[row * 128 + col] = make_float2(v0, v1);
                } else if (warp_n == 0) {
                    *(float2*)&O0[row * 64 + col] = make_float2(v0, v1);
                } else {
                    int cb = col - 64;
                    v0 += sb[cb];
                    v1 += sb[cb + 1];
                    *(float2*)&O1[row * 64 + cb] = make_float2(v0, v1);
                }
            }
        }
    }
}

// ---------------- launch ----------------

extern "C" void kernel_launch(void* const* d_in, const int* in_sizes, int n_in,
                              void* d_out, int out_size) {
    const float* x = (const float*)d_in[0];
    const void* ei = d_in[1];
    const float* W1l = (const float*)d_in[2];
    const float* W1r = (const float*)d_in[3];
    const float* b1 = (const float*)d_in[4];
    const float* W2l = (const float*)d_in[5];
    const float* W2r = (const float*)d_in[6];
    const float* b2 = (const float*)d_in[7];
    float* out = (float*)d_out;

    int n = in_sizes[0] / 64;
    int E = in_sizes[1] / 2;

    float* agg;  cudaGetSymbolAddress((void**)&agg, g_agg);
    float* h;    cudaGetSymbolAddress((void**)&h, g_h);
    float* t;    cudaGetSymbolAddress((void**)&t, g_t);

    cudaFuncSetAttribute(k_mma, cudaFuncAttributeMaxDynamicSharedMemorySize, SMEM_MMA_BYTES);

    int nb = (n + 1023) / 1024;
    int ntile = (n + 127) / 128;

    k_init<<<(n + 255) / 256, 256>>>((const int*)ei, n);
    k_hist<<<(E + 255) / 256, 256>>>(ei, E, n);
    k_wconv<<<32, 256>>>(0, W1l, W1r);
    k_wconv<<<32, 256>>>(1, W2l, W2r);
    k_scanA<<<nb, 1024>>>(n);
    k_scanB<<<1, 1024>>>(nb);
    k_scanC<<<(n + 255) / 256, 256>>>(n, E);
    k_fill<<<(E + 255) / 256, 256>>>(E);

    // layer 1
    k_aggmean<<<(n * 32 + 255) / 256, 256>>>(x, agg, n);
    k_mma<<<ntile, 256, SMEM_MMA_BYTES>>>(0, agg, x, b1, h, nullptr, n);

    // layer 2
    k_mma<<<ntile, 256, SMEM_MMA_BYTES>>>(1, h, nullptr, b2, t, out, n);
    k_aggmean_add<<<(n * 32 + 255) / 256, 256>>>(t, out, n);
}

// round 16
// speedup vs baseline: 1.1116x; 1.0214x over previous
#include <cuda_runtime.h>
#include <cuda_fp16.h>
#include <cstdint>

// GraphSAGE 2-layer.
//   L1: agg1 = segmean(x); h = relu([agg1|x] @ [W1l;W1r] + b1)   (agg fused into GEMM1)
//   L2: t = h@W2l; hr = h@W2r + b2; out = segmean(t) + hr
// GEMMs: mma.sync m16n8k16 pure fp16 (fp32 accum). rel_err budget ~5e-4.

#define MAXN 100000
#define MAXE 1600000

__device__ int     g_is64;
__device__ int     g_src[MAXE];
__device__ int     g_dst[MAXE];
__device__ int     g_cnt[MAXN];
__device__ int     g_row[MAXN + 1];
__device__ int     g_next[MAXN];
__device__ int     g_col[MAXE];
__device__ int     g_bs[1024];
__device__ int     g_bo[1024];
__device__ float   g_h[MAXN * 128];
__device__ float   g_t[MAXN * 64];
// fp16 weight tiles, one per layer: [n:128][kw:64 words]
__device__ uint32_t g_wb[2][128 * 64];

__device__ __forceinline__ uint32_t pack_h2(float a, float b) {
    __half h0 = __float2half_rn(a);
    __half h1 = __float2half_rn(b);
    return (uint32_t)__half_as_ushort(h0) | ((uint32_t)__half_as_ushort(h1) << 16);
}

// ---------------- init: zero counts + edge dtype detect ----------------

__global__ void k_init(const int* __restrict__ ei32, int n) {
    int i = blockIdx.x * blockDim.x + threadIdx.x;
    if (i < n) g_cnt[i] = 0;
    if (i == 0) {
        int s = 0;
        #pragma unroll
        for (int j = 0; j < 64; j++) s |= ei32[2 * j + 1];
        g_is64 = (s == 0) ? 1 : 0;
    }
}

// ---------------- CSR build ----------------

__global__ void k_hist(const void* __restrict__ ei, int E, int n) {
    int e = (blockIdx.x * blockDim.x + threadIdx.x) * 2;
    if (e >= E) return;
    if (e + 1 < E) {
        int s0, s1, d0, d1;
        if (g_is64) {
            longlong2 sv = __ldg((const longlong2*)((const long long*)ei + e));
            longlong2 dv = __ldg((const longlong2*)((const long long*)ei + E + e));
            s0 = (int)sv.x; s1 = (int)sv.y; d0 = (int)dv.x; d1 = (int)dv.y;
        } else {
            int2 sv = __ldg((const int2*)((const int*)ei + e));
            int2 dv = __ldg((const int2*)((const int*)ei + E + e));
            s0 = sv.x; s1 = sv.y; d0 = dv.x; d1 = dv.y;
        }
        s0 = min(max(s0, 0), n - 1); s1 = min(max(s1, 0), n - 1);
        d0 = min(max(d0, 0), n - 1); d1 = min(max(d1, 0), n - 1);
        *(int2*)&g_src[e] = make_int2(s0, s1);
        *(int2*)&g_dst[e] = make_int2(d0, d1);
        atomicAdd(&g_cnt[d0], 1);
        atomicAdd(&g_cnt[d1], 1);
    } else {
        int s, d;
        if (g_is64) {
            s = (int)__ldg((const long long*)ei + e);
            d = (int)__ldg((const long long*)ei + E + e);
        } else {
            s = __ldg((const int*)ei + e);
            d = __ldg((const int*)ei + E + e);
        }
        s = min(max(s, 0), n - 1);
        d = min(max(d, 0), n - 1);
        g_src[e] = s;
        g_dst[e] = d;
        atomicAdd(&g_cnt[d], 1);
    }
}

__global__ void k_scanA(int n) {
    __shared__ int s[1024];
    int i = blockIdx.x * 1024 + threadIdx.x;
    int v = (i < n) ? g_cnt[i] : 0;
    s[threadIdx.x] = v;
    __syncthreads();
    for (int off = 1; off < 1024; off <<= 1) {
        int t = (threadIdx.x >= off) ? s[threadIdx.x - off] : 0;
        __syncthreads();
        s[threadIdx.x] += t;
        __syncthreads();
    }
    if (i < n) g_row[i] = s[threadIdx.x] - v;
    if (threadIdx.x == 1023) g_bs[blockIdx.x] = s[1023];
}

__global__ void k_scanB(int nb) {
    __shared__ int s[1024];
    int v = (threadIdx.x < nb) ? g_bs[threadIdx.x] : 0;
    s[threadIdx.x] = v;
    __syncthreads();
    for (int off = 1; off < 1024; off <<= 1) {
        int t = (threadIdx.x >= off) ? s[threadIdx.x - off] : 0;
        __syncthreads();
        s[threadIdx.x] += t;
        __syncthreads();
    }
    g_bo[threadIdx.x] = s[threadIdx.x] - v;
}

__global__ void k_scanC(int n, int E) {
    int i = blockIdx.x * blockDim.x + threadIdx.x;
    if (i < n) {
        int r = g_row[i] + g_bo[i >> 10];
        g_row[i] = r;
        g_next[i] = r;
    }
    if (i == 0) g_row[n] = E;
}

__global__ void k_fill(int E) {
    int e = blockIdx.x * blockDim.x + threadIdx.x;
    if (e < E) {
        int p = atomicAdd(&g_next[g_dst[e]], 1);
        g_col[p] = g_src[e];
    }
}

// ---------------- segment mean pass 2 (reads t, adds into out) ----------------

__global__ void k_aggmean_add(const float* __restrict__ src, float* __restrict__ out, int n) {
    int w = (blockIdx.x * blockDim.x + threadIdx.x) >> 5;
    int lane = threadIdx.x & 31;
    if (w >= n) return;
    int beg = g_row[w], end = g_row[w + 1];
    const float2* s2 = (const float2*)src;
    float sx = 0.f, sy = 0.f;
    int j = beg;
    for (; j + 8 <= end; j += 8) {
        int c[8];
        #pragma unroll
        for (int q = 0; q < 8; q++) c[q] = __ldg(&g_col[j + q]);
        float2 v[8];
        #pragma unroll
        for (int q = 0; q < 8; q++) v[q] = __ldg(&s2[c[q] * 32 + lane]);
        #pragma unroll
        for (int q = 0; q < 8; q++) { sx += v[q].x; sy += v[q].y; }
    }
    for (; j + 2 <= end; j += 2) {
        int c0 = __ldg(&g_col[j]);
        int c1 = __ldg(&g_col[j + 1]);
        float2 v0 = __ldg(&s2[c0 * 32 + lane]);
        float2 v1 = __ldg(&s2[c1 * 32 + lane]);
        sx += v0.x + v1.x;
        sy += v0.y + v1.y;
    }
    for (; j < end; j++) {
        int c = __ldg(&g_col[j]);
        float2 v = __ldg(&s2[c * 32 + lane]);
        sx += v.x;
        sy += v.y;
    }
    int deg = end - beg;
    float inv = 1.0f / (float)(deg > 0 ? deg : 1);
    float2* o2 = (float2*)out;
    float2 cur = o2[w * 32 + lane];
    cur.x += sx * inv;
    cur.y += sy * inv;
    o2[w * 32 + lane] = cur;
}

// ---------------- weight precompute (both layers in one launch) ----------------

__global__ void k_wconv(const float* __restrict__ W1l, const float* __restrict__ W1r,
                        const float* __restrict__ W2l, const float* __restrict__ W2r) {
    int mode = (blockIdx.x >= 32) ? 1 : 0;
    int i = (blockIdx.x & 31) * blockDim.x + threadIdx.x;
    if (i >= 128 * 64) return;
    int nn = i >> 6;
    int k = (i & 63) * 2;
    float w0, w1;
    if (mode == 0) {
        w0 = (k < 64) ? W1l[k * 128 + nn] : W1r[(k - 64) * 128 + nn];
        w1 = (k + 1 < 64) ? W1l[(k + 1) * 128 + nn] : W1r[(k + 1 - 64) * 128 + nn];
    } else {
        const float* W = (nn < 64) ? W2l : W2r;
        int c = (nn < 64) ? nn : nn - 64;
        w0 = W[k * 64 + c];
        w1 = W[(k + 1) * 64 + c];
    }
    g_wb[mode][i] = pack_h2(w0, w1);
}

// ---------------- GEMM: D[128,128] = A @ B^T, pure fp16, fp32 accum ----------------
// mode 0: A cols k<64 = segmean(x) (GATHERED IN-KERNEL), k>=64 = x. h = relu(D+b1).
// mode 1: A = h. cols<64 -> t = D; cols>=64 -> out = D + b2.

#define KW 68
#define SM_AH 0
#define SM_BH (128 * KW)
#define SM_BIAS (2 * 128 * KW)
#define SMEM_WORDS (2 * 128 * KW + 128)
#define SMEM_MMA_BYTES (SMEM_WORDS * 4)

__global__ void __launch_bounds__(256, 2)
k_mma(int mode, const float* __restrict__ A0,
      const float* __restrict__ bias, float* __restrict__ O0, float* __restrict__ O1, int n)
{
    extern __shared__ uint32_t sm4[];
    int tid = threadIdx.x, wid = tid >> 5, lane = tid & 31;
    int row0 = blockIdx.x * 128;
    const uint32_t* wb = g_wb[mode];
    const float2* s2 = (const float2*)A0;

    if (mode == 0) {
        // ---- fused gather: agg columns (kw 0..31), warp per node ----
        for (int it = 0; it < 16; it++) {
            int m = wid * 16 + it;
            int row = row0 + m;
            float sx = 0.f, sy = 0.f;
            if (row < n) {
                int beg = __ldg(&g_row[row]), end = __ldg(&g_row[row + 1]);
                int j = beg;
                for (; j + 8 <= end; j += 8) {
                    int c[8];
                    #pragma unroll
                    for (int q = 0; q < 8; q++) c[q] = __ldg(&g_col[j + q]);
                    float2 v[8];
                    #pragma unroll
                    for (int q = 0; q < 8; q++) v[q] = __ldg(&s2[c[q] * 32 + lane]);
                    #pragma unroll
                    for (int q = 0; q < 8; q++) { sx += v[q].x; sy += v[q].y; }
                }
                for (; j < end; j++) {
                    int c = __ldg(&g_col[j]);
                    float2 v = __ldg(&s2[c * 32 + lane]);
                    sx += v.x;
                    sy += v.y;
                }
                int deg = end - beg;
                float inv = 1.0f / (float)(deg > 0 ? deg : 1);
                sx *= inv;
                sy *= inv;
            }
            sm4[SM_AH + m * KW + lane] = pack_h2(sx, sy);
        }
        // ---- x columns (kw 32..63) ----
        for (int i = tid; i < 128 * 32; i += 256) {
            int m = i >> 5, kwl = i & 31;
            int row = row0 + m;
            float2 v = make_float2(0.f, 0.f);
            if (row < n) v = __ldg(&s2[row * 32 + kwl]);
            sm4[SM_AH + m * KW + 32 + kwl] = pack_h2(v.x, v.y);
        }
    } else {
        for (int i = tid; i < 128 * 64; i += 256) {
            int m = i >> 6, kw = i & 63;
            int row = row0 + m;
            float2 v = make_float2(0.f, 0.f);
            if (row < n) v = __ldg(&s2[row * 64 + kw]);
            sm4[SM_AH + m * KW + kw] = pack_h2(v.x, v.y);
        }
    }
    // ---- B tile ----
    for (int i = tid; i < 128 * 64; i += 256) {
        int nn = i >> 6, kw = i & 63;
        sm4[SM_BH + nn * KW + kw] = wb[i];
    }
    if (tid < 128) {
        float bv = 0.f;
        if (mode == 0) bv = __ldg(&bias[tid]);
        else if (tid < 64) bv = __ldg(&bias[tid]);
        ((float*)(sm4 + SM_BIAS))[tid] = bv;
    }
    __syncthreads();

    int warp_m = wid & 3, warp_n = wid >> 2;
    int lr = lane >> 2;
    int lc = lane & 3;

    float acc[2][8][4];
    #pragma unroll
    for (int mt = 0; mt < 2; mt++)
        #pragma unroll
        for (int nt = 0; nt < 8; nt++)
            #pragma unroll
            for (int q = 0; q < 4; q++) acc[mt][nt][q] = 0.f;

    int a_row_in_tile = lane & 15;
    int a_kw_off = (lane >> 4) << 2;
    int b_row_in_grp = (lane & 7) + ((lane >> 4) << 3);
    int b_kw_off = ((lane >> 3) & 1) << 2;

    const uint32_t* Ap = sm4 + SM_AH;
    const uint32_t* Bp = sm4 + SM_BH;
    #pragma unroll
    for (int ks = 0; ks < 8; ks++) {
        int kwb = ks * 8;
        uint32_t a[2][4];
        #pragma unroll
        for (int mt = 0; mt < 2; mt++) {
            int r = warp_m * 32 + mt * 16 + a_row_in_tile;
            uint32_t addr = (uint32_t)__cvta_generic_to_shared(&Ap[r * KW + kwb + a_kw_off]);
            asm volatile("ldmatrix.sync.aligned.m8n8.x4.shared.b16 {%0,%1,%2,%3}, [%4];"
                         : "=r"(a[mt][0]), "=r"(a[mt][1]), "=r"(a[mt][2]), "=r"(a[mt][3])
                         : "r"(addr));
        }
        uint32_t br[4][4];
        #pragma unroll
        for (int ng = 0; ng < 4; ng++) {
            int nb = warp_n * 64 + ng * 16 + b_row_in_grp;
            uint32_t addr = (uint32_t)__cvta_generic_to_shared(&Bp[nb * KW + kwb + b_kw_off]);
            asm volatile("ldmatrix.sync.aligned.m8n8.x4.shared.b16 {%0,%1,%2,%3}, [%4];"
                         : "=r"(br[ng][0]), "=r"(br[ng][1]), "=r"(br[ng][2]), "=r"(br[ng][3])
                         : "r"(addr));
        }
        #pragma unroll
        for (int ng = 0; ng < 4; ng++) {
            #pragma unroll
            for (int sub = 0; sub < 2; sub++) {
                int nt = ng * 2 + sub;
                uint32_t b0 = br[ng][sub * 2], b1 = br[ng][sub * 2 + 1];
                #pragma unroll
                for (int mt = 0; mt < 2; mt++) {
                    asm volatile(
                        "mma.sync.aligned.m16n8k16.row.col.f32.f16.f16.f32 "
                        "{%0,%1,%2,%3}, {%4,%5,%6,%7}, {%8,%9}, {%0,%1,%2,%3};"
                        : "+f"(acc[mt][nt][0]), "+f"(acc[mt][nt][1]),
                          "+f"(acc[mt][nt][2]), "+f"(acc[mt][nt][3])
                        : "r"(a[mt][0]), "r"(a[mt][1]), "r"(a[mt][2]), "r"(a[mt][3]),
                          "r"(b0), "r"(b1));
                }
            }
        }
    }

    const float* sb = (const float*)(sm4 + SM_BIAS);
    #pragma unroll
    for (int mt = 0; mt < 2; mt++) {
        int rbase = row0 + warp_m * 32 + mt * 16 + lr;
        #pragma unroll
        for (int nt = 0; nt < 8; nt++) {
            int col = warp_n * 64 + nt * 8 + lc * 2;
            #pragma unroll
            for (int half = 0; half < 2; half++) {
                int row = rbase + half * 8;
                if (row >= n) continue;
                float v0 = acc[mt][nt][half * 2 + 0];
                float v1 = acc[mt][nt][half * 2 + 1];
                if (mode == 0) {
                    v0 = fmaxf(v0 + sb[col], 0.f);
                    v1 = fmaxf(v1 + sb[col + 1], 0.f);
                    *(float2*)&O0[row * 128 + col] = make_float2(v0, v1);
                } else if (warp_n == 0) {
                    *(float2*)&O0[row * 64 + col] = make_float2(v0, v1);
                } else {
                    int cb = col - 64;
                    v0 += sb[cb];
                    v1 += sb[cb + 1];
                    *(float2*)&O1[row * 64 + cb] = make_float2(v0, v1);
                }
            }
        }
    }
}

// ---------------- launch ----------------

extern "C" void kernel_launch(void* const* d_in, const int* in_sizes, int n_in,
                              void* d_out, int out_size) {
    const float* x = (const float*)d_in[0];
    const void* ei = d_in[1];
    const float* W1l = (const float*)d_in[2];
    const float* W1r = (const float*)d_in[3];
    const float* b1 = (const float*)d_in[4];
    const float* W2l = (const float*)d_in[5];
    const float* W2r = (const float*)d_in[6];
    const float* b2 = (const float*)d_in[7];
    float* out = (float*)d_out;

    int n = in_sizes[0] / 64;
    int E = in_sizes[1] / 2;

    float* h;  cudaGetSymbolAddress((void**)&h, g_h);
    float* t;  cudaGetSymbolAddress((void**)&t, g_t);

    cudaFuncSetAttribute(k_mma, cudaFuncAttributeMaxDynamicSharedMemorySize, SMEM_MMA_BYTES);

    int nb = (n + 1023) / 1024;
    int ntile = (n + 127) / 128;

    k_init<<<(n + 255) / 256, 256>>>((const int*)ei, n);
    k_hist<<<(E / 2 + 255) / 256, 256>>>(ei, E, n);
    k_wconv<<<64, 256>>>(W1l, W1r, W2l, W2r);
    k_scanA<<<nb, 1024>>>(n);
    k_scanB<<<1, 1024>>>(nb);
    k_scanC<<<(n + 255) / 256, 256>>>(n, E);
    k_fill<<<(E + 255) / 256, 256>>>(E);

    // layer 1 (aggregation fused into GEMM)
    k_mma<<<ntile, 256, SMEM_MMA_BYTES>>>(0, x, b1, h, nullptr, n);

    // layer 2
    k_mma<<<ntile, 256, SMEM_MMA_BYTES>>>(1, h, b2, t, out, n);
    k_aggmean_add<<<(n * 32 + 255) / 256, 256>>>(t, out, n);
}

// round 17
// speedup vs baseline: 1.1406x; 1.0260x over previous
#include <cuda_runtime.h>
#include <cuda_fp16.h>
#include <cstdint>

// GraphSAGE 2-layer.
//   L1: agg1 = segmean(x); h = relu([agg1|x] @ [W1l;W1r] + b1)   (agg fused into GEMM1)
//   L2: t = h@W2l; hr = h@W2r + b2; out = segmean(t) + hr
// GEMMs: mma.sync m16n8k16 pure fp16 (fp32 accum).
// Feature tables x,h,t kept in fp16 (halved gather traffic); h/t written coalesced
// via smem staging. CSR fill is atomic-free (rank captured during histogram).

#define MAXN 100000
#define MAXE 1600000

__device__ int      g_is64;
__device__ int      g_src[MAXE];
__device__ int      g_dst[MAXE];
__device__ int      g_rank[MAXE];
__device__ int      g_cnt[MAXN];
__device__ int      g_row[MAXN + 1];
__device__ int      g_col[MAXE];
__device__ int      g_bs[1024];
__device__ int      g_bo[1024];
__device__ uint32_t g_xh[MAXN * 32];   // x as half2 words [n][32]
__device__ uint32_t g_hh[MAXN * 64];   // h as half2 words [n][64]
__device__ uint32_t g_th[MAXN * 32];   // t as half2 words [n][32]
__device__ uint32_t g_wb[2][128 * 64]; // fp16 weight tiles [n:128][kw:64]

__device__ __forceinline__ uint32_t pack_h2(float a, float b) {
    __half h0 = __float2half_rn(a);
    __half h1 = __float2half_rn(b);
    return (uint32_t)__half_as_ushort(h0) | ((uint32_t)__half_as_ushort(h1) << 16);
}
__device__ __forceinline__ float2 unpack_h2(uint32_t w) {
    return __half22float2(*(__half2*)&w);
}

// ---------------- init: zero counts + edge dtype detect ----------------

__global__ void k_init(const int* __restrict__ ei32, int n) {
    int i = blockIdx.x * blockDim.x + threadIdx.x;
    if (i < n) g_cnt[i] = 0;
    if (i == 0) {
        int s = 0;
        #pragma unroll
        for (int j = 0; j < 64; j++) s |= ei32[2 * j + 1];
        g_is64 = (s == 0) ? 1 : 0;
    }
}

// ---------------- x -> fp16 ----------------

__global__ void k_xconv(const float* __restrict__ x, int n) {
    int i = blockIdx.x * blockDim.x + threadIdx.x;
    if (i < n * 32) {
        float2 v = __ldg(&((const float2*)x)[i]);
        g_xh[i] = pack_h2(v.x, v.y);
    }
}

// ---------------- CSR build ----------------

__global__ void k_hist(const void* __restrict__ ei, int E, int n) {
    int e = (blockIdx.x * blockDim.x + threadIdx.x) * 2;
    if (e >= E) return;
    if (e + 1 < E) {
        int s0, s1, d0, d1;
        if (g_is64) {
            longlong2 sv = __ldg((const longlong2*)((const long long*)ei + e));
            longlong2 dv = __ldg((const longlong2*)((const long long*)ei + E + e));
            s0 = (int)sv.x; s1 = (int)sv.y; d0 = (int)dv.x; d1 = (int)dv.y;
        } else {
            int2 sv = __ldg((const int2*)((const int*)ei + e));
            int2 dv = __ldg((const int2*)((const int*)ei + E + e));
            s0 = sv.x; s1 = sv.y; d0 = dv.x; d1 = dv.y;
        }
        s0 = min(max(s0, 0), n - 1); s1 = min(max(s1, 0), n - 1);
        d0 = min(max(d0, 0), n - 1); d1 = min(max(d1, 0), n - 1);
        *(int2*)&g_src[e] = make_int2(s0, s1);
        *(int2*)&g_dst[e] = make_int2(d0, d1);
        int r0 = atomicAdd(&g_cnt[d0], 1);
        int r1 = atomicAdd(&g_cnt[d1], 1);
        *(int2*)&g_rank[e] = make_int2(r0, r1);
    } else {
        int s, d;
        if (g_is64) {
            s = (int)__ldg((const long long*)ei + e);
            d = (int)__ldg((const long long*)ei + E + e);
        } else {
            s = __ldg((const int*)ei + e);
            d = __ldg((const int*)ei + E + e);
        }
        s = min(max(s, 0), n - 1);
        d = min(max(d, 0), n - 1);
        g_src[e] = s;
        g_dst[e] = d;
        g_rank[e] = atomicAdd(&g_cnt[d], 1);
    }
}

__global__ void k_scanA(int n) {
    __shared__ int s[1024];
    int i = blockIdx.x * 1024 + threadIdx.x;
    int v = (i < n) ? g_cnt[i] : 0;
    s[threadIdx.x] = v;
    __syncthreads();
    for (int off = 1; off < 1024; off <<= 1) {
        int t = (threadIdx.x >= off) ? s[threadIdx.x - off] : 0;
        __syncthreads();
        s[threadIdx.x] += t;
        __syncthreads();
    }
    if (i < n) g_row[i] = s[threadIdx.x] - v;
    if (threadIdx.x == 1023) g_bs[blockIdx.x] = s[1023];
}

__global__ void k_scanB(int nb) {
    __shared__ int s[1024];
    int v = (threadIdx.x < nb) ? g_bs[threadIdx.x] : 0;
    s[threadIdx.x] = v;
    __syncthreads();
    for (int off = 1; off < 1024; off <<= 1) {
        int t = (threadIdx.x >= off) ? s[threadIdx.x - off] : 0;
        __syncthreads();
        s[threadIdx.x] += t;
        __syncthreads();
    }
    g_bo[threadIdx.x] = s[threadIdx.x] - v;
}

__global__ void k_scanC(int n, int E) {
    int i = blockIdx.x * blockDim.x + threadIdx.x;
    if (i < n) g_row[i] += g_bo[i >> 10];
    if (i == 0) g_row[n] = E;
}

// atomic-free fill: pos = row[dst] + rank
__global__ void k_fill(int E) {
    int e = (blockIdx.x * blockDim.x + threadIdx.x) * 2;
    if (e >= E) return;
    if (e + 1 < E) {
        int2 d = *(const int2*)&g_dst[e];
        int2 r = *(const int2*)&g_rank[e];
        int2 s = *(const int2*)&g_src[e];
        g_col[__ldg(&g_row[d.x]) + r.x] = s.x;
        g_col[__ldg(&g_row[d.y]) + r.y] = s.y;
    } else {
        g_col[__ldg(&g_row[g_dst[e]]) + g_rank[e]] = g_src[e];
    }
}

// ---------------- segment mean pass 2 (reads t fp16, adds into out) ----------------

__global__ void k_aggmean_add(float* __restrict__ out, int n) {
    int w = (blockIdx.x * blockDim.x + threadIdx.x) >> 5;
    int lane = threadIdx.x & 31;
    if (w >= n) return;
    int beg = g_row[w], end = g_row[w + 1];
    float sx = 0.f, sy = 0.f;
    int j = beg;
    for (; j + 8 <= end; j += 8) {
        int c[8];
        #pragma unroll
        for (int q = 0; q < 8; q++) c[q] = __ldg(&g_col[j + q]);
        uint32_t v[8];
        #pragma unroll
        for (int q = 0; q < 8; q++) v[q] = __ldg(&g_th[c[q] * 32 + lane]);
        #pragma unroll
        for (int q = 0; q < 8; q++) { float2 f = unpack_h2(v[q]); sx += f.x; sy += f.y; }
    }
    for (; j < end; j++) {
        int c = __ldg(&g_col[j]);
        float2 f = unpack_h2(__ldg(&g_th[c * 32 + lane]));
        sx += f.x;
        sy += f.y;
    }
    int deg = end - beg;
    float inv = 1.0f / (float)(deg > 0 ? deg : 1);
    float2* o2 = (float2*)out;
    float2 cur = o2[w * 32 + lane];
    cur.x += sx * inv;
    cur.y += sy * inv;
    o2[w * 32 + lane] = cur;
}

// ---------------- weight precompute (both layers, one launch) ----------------

__global__ void k_wconv(const float* __restrict__ W1l, const float* __restrict__ W1r,
                        const float* __restrict__ W2l, const float* __restrict__ W2r) {
    int mode = (blockIdx.x >= 32) ? 1 : 0;
    int i = (blockIdx.x & 31) * blockDim.x + threadIdx.x;
    if (i >= 128 * 64) return;
    int nn = i >> 6;
    int k = (i & 63) * 2;
    float w0, w1;
    if (mode == 0) {
        w0 = (k < 64) ? W1l[k * 128 + nn] : W1r[(k - 64) * 128 + nn];
        w1 = (k + 1 < 64) ? W1l[(k + 1) * 128 + nn] : W1r[(k + 1 - 64) * 128 + nn];
    } else {
        const float* W = (nn < 64) ? W2l : W2r;
        int c = (nn < 64) ? nn : nn - 64;
        w0 = W[k * 64 + c];
        w1 = W[(k + 1) * 64 + c];
    }
    g_wb[mode][i] = pack_h2(w0, w1);
}

// ---------------- GEMM: D[128,128] = A @ B^T, fp16, fp32 accum ----------------
// mode 0: A k<64 = segmean(xh) gathered in-kernel, k>=64 = xh copy. h(fp16) = relu(D+b1).
// mode 1: A = hh (raw copy). cols<64 -> th (fp16); cols>=64 -> out = D + b2 (fp32).

#define KW 68
#define SM_AH 0
#define SM_BH (128 * KW)
#define SM_BIAS (2 * 128 * KW)
#define SMEM_WORDS (2 * 128 * KW + 128)
#define SMEM_MMA_BYTES (SMEM_WORDS * 4)

__global__ void __launch_bounds__(256, 2)
k_mma(int mode, const float* __restrict__ bias, float* __restrict__ Oout, int n)
{
    extern __shared__ uint32_t sm4[];
    int tid = threadIdx.x, wid = tid >> 5, lane = tid & 31;
    int row0 = blockIdx.x * 128;
    const uint32_t* wb = g_wb[mode];

    if (mode == 0) {
        // fused gather: agg cols (kw 0..31), warp per node
        for (int it = 0; it < 16; it++) {
            int m = wid * 16 + it;
            int row = row0 + m;
            float sx = 0.f, sy = 0.f;
            if (row < n) {
                int beg = __ldg(&g_row[row]), end = __ldg(&g_row[row + 1]);
                int j = beg;
                for (; j + 8 <= end; j += 8) {
                    int c[8];
                    #pragma unroll
                    for (int q = 0; q < 8; q++) c[q] = __ldg(&g_col[j + q]);
                    uint32_t v[8];
                    #pragma unroll
                    for (int q = 0; q < 8; q++) v[q] = __ldg(&g_xh[c[q] * 32 + lane]);
                    #pragma unroll
                    for (int q = 0; q < 8; q++) { float2 f = unpack_h2(v[q]); sx += f.x; sy += f.y; }
                }
                for (; j < end; j++) {
                    int c = __ldg(&g_col[j]);
                    float2 f = unpack_h2(__ldg(&g_xh[c * 32 + lane]));
                    sx += f.x;
                    sy += f.y;
                }
                int deg = end - beg;
                float inv = 1.0f / (float)(deg > 0 ? deg : 1);
                sx *= inv;
                sy *= inv;
            }
            sm4[SM_AH + m * KW + lane] = pack_h2(sx, sy);
        }
        // x cols (kw 32..63): raw fp16 copy
        for (int i = tid; i < 128 * 32; i += 256) {
            int m = i >> 5, kwl = i & 31;
            int row = row0 + m;
            sm4[SM_AH + m * KW + 32 + kwl] = (row < n) ? __ldg(&g_xh[row * 32 + kwl]) : 0u;
        }
    } else {
        // A = h, raw fp16 copy
        for (int i = tid; i < 128 * 64; i += 256) {
            int m = i >> 6, kw = i & 63;
            int row = row0 + m;
            sm4[SM_AH + m * KW + kw] = (row < n) ? __ldg(&g_hh[row * 64 + kw]) : 0u;
        }
    }
    for (int i = tid; i < 128 * 64; i += 256) {
        int nn = i >> 6, kw = i & 63;
        sm4[SM_BH + nn * KW + kw] = wb[i];
    }
    if (tid < 128) {
        float bv = 0.f;
        if (mode == 0) bv = __ldg(&bias[tid]);
        else if (tid < 64) bv = __ldg(&bias[tid]);
        ((float*)(sm4 + SM_BIAS))[tid] = bv;
    }
    __syncthreads();

    int warp_m = wid & 3, warp_n = wid >> 2;
    int lr = lane >> 2;
    int lc = lane & 3;

    float acc[2][8][4];
    #pragma unroll
    for (int mt = 0; mt < 2; mt++)
        #pragma unroll
        for (int nt = 0; nt < 8; nt++)
            #pragma unroll
            for (int q = 0; q < 4; q++) acc[mt][nt][q] = 0.f;

    int a_row_in_tile = lane & 15;
    int a_kw_off = (lane >> 4) << 2;
    int b_row_in_grp = (lane & 7) + ((lane >> 4) << 3);
    int b_kw_off = ((lane >> 3) & 1) << 2;

    const uint32_t* Ap = sm4 + SM_AH;
    const uint32_t* Bp = sm4 + SM_BH;
    #pragma unroll
    for (int ks = 0; ks < 8; ks++) {
        int kwb = ks * 8;
        uint32_t a[2][4];
        #pragma unroll
        for (int mt = 0; mt < 2; mt++) {
            int r = warp_m * 32 + mt * 16 + a_row_in_tile;
            uint32_t addr = (uint32_t)__cvta_generic_to_shared(&Ap[r * KW + kwb + a_kw_off]);
            asm volatile("ldmatrix.sync.aligned.m8n8.x4.shared.b16 {%0,%1,%2,%3}, [%4];"
                         : "=r"(a[mt][0]), "=r"(a[mt][1]), "=r"(a[mt][2]), "=r"(a[mt][3])
                         : "r"(addr));
        }
        uint32_t br[4][4];
        #pragma unroll
        for (int ng = 0; ng < 4; ng++) {
            int nb = warp_n * 64 + ng * 16 + b_row_in_grp;
            uint32_t addr = (uint32_t)__cvta_generic_to_shared(&Bp[nb * KW + kwb + b_kw_off]);
            asm volatile("ldmatrix.sync.aligned.m8n8.x4.shared.b16 {%0,%1,%2,%3}, [%4];"
                         : "=r"(br[ng][0]), "=r"(br[ng][1]), "=r"(br[ng][2]), "=r"(br[ng][3])
                         : "r"(addr));
        }
        #pragma unroll
        for (int ng = 0; ng < 4; ng++) {
            #pragma unroll
            for (int sub = 0; sub < 2; sub++) {
                int nt = ng * 2 + sub;
                uint32_t b0 = br[ng][sub * 2], b1 = br[ng][sub * 2 + 1];
                #pragma unroll
                for (int mt = 0; mt < 2; mt++) {
                    asm volatile(
                        "mma.sync.aligned.m16n8k16.row.col.f32.f16.f16.f32 "
                        "{%0,%1,%2,%3}, {%4,%5,%6,%7}, {%8,%9}, {%0,%1,%2,%3};"
                        : "+f"(acc[mt][nt][0]), "+f"(acc[mt][nt][1]),
                          "+f"(acc[mt][nt][2]), "+f"(acc[mt][nt][3])
                        : "r"(a[mt][0]), "r"(a[mt][1]), "r"(a[mt][2]), "r"(a[mt][3]),
                          "r"(b0), "r"(b1));
                }
            }
        }
    }

    const float* sb = (const float*)(sm4 + SM_BIAS);

    if (mode == 0) {
        // stage h (fp16) into smem with padded stride 65, then coalesced store
        __syncthreads();  // A/B consumption done
        #pragma unroll
        for (int mt = 0; mt < 2; mt++) {
            #pragma unroll
            for (int nt = 0; nt < 8; nt++) {
                int col = warp_n * 64 + nt * 8 + lc * 2;
                #pragma unroll
                for (int half = 0; half < 2; half++) {
                    int m = warp_m * 32 + mt * 16 + lr + half * 8;
                    float v0 = fmaxf(acc[mt][nt][half * 2 + 0] + sb[col], 0.f);
                    float v1 = fmaxf(acc[mt][nt][half * 2 + 1] + sb[col + 1], 0.f);
                    sm4[m * 65 + (col >> 1)] = pack_h2(v0, v1);
                }
            }
        }
        __syncthreads();
        for (int i = tid; i < 128 * 64; i += 256) {
            int m = i >> 6, w = i & 63;
            int row = row0 + m;
            if (row < n) g_hh[row * 64 + w] = sm4[m * 65 + w];
        }
    } else {
        // out cols (>=64): direct fp32 store; t cols (<64): stage fp16, stride 33
        #pragma unroll
        for (int mt = 0; mt < 2; mt++) {
            #pragma unroll
            for (int nt = 0; nt < 8; nt++) {
                int col = warp_n * 64 + nt * 8 + lc * 2;
                #pragma unroll
                for (int half = 0; half < 2; half++) {
                    int m = warp_m * 32 + mt * 16 + lr + half * 8;
                    int row = row0 + m;
                    if (warp_n == 1 && row < n) {
                        int cb = col - 64;
                        float v0 = acc[mt][nt][half * 2 + 0] + sb[cb];
                        float v1 = acc[mt][nt][half * 2 + 1] + sb[cb + 1];
                        *(float2*)&Oout[row * 64 + cb] = make_float2(v0, v1);
                    }
                }
            }
        }
        __syncthreads();
        if (warp_n == 0) {
            #pragma unroll
            for (int mt = 0; mt < 2; mt++) {
                #pragma unroll
                for (int nt = 0; nt < 8; nt++) {
                    int col = nt * 8 + lc * 2;
                    #pragma unroll
                    for (int half = 0; half < 2; half++) {
                        int m = warp_m * 32 + mt * 16 + lr + half * 8;
                        sm4[m * 33 + (col >> 1)] =
                            pack_h2(acc[mt][nt][half * 2 + 0], acc[mt][nt][half * 2 + 1]);
                    }
                }
            }
        }
        __syncthreads();
        for (int i = tid; i < 128 * 32; i += 256) {
            int m = i >> 5, w = i & 31;
            int row = row0 + m;
            if (row < n) g_th[row * 32 + w] = sm4[m * 33 + w];
        }
    }
}

// ---------------- launch ----------------

extern "C" void kernel_launch(void* const* d_in, const int* in_sizes, int n_in,
                              void* d_out, int out_size) {
    const float* x = (const float*)d_in[0];
    const void* ei = d_in[1];
    const float* W1l = (const float*)d_in[2];
    const float* W1r = (const float*)d_in[3];
    const float* b1 = (const float*)d_in[4];
    const float* W2l = (const float*)d_in[5];
    const float* W2r = (const float*)d_in[6];
    const float* b2 = (const float*)d_in[7];
    float* out = (float*)d_out;

    int n = in_sizes[0] / 64;
    int E = in_sizes[1] / 2;

    cudaFuncSetAttribute(k_mma, cudaFuncAttributeMaxDynamicSharedMemorySize, SMEM_MMA_BYTES);

    int nb = (n + 1023) / 1024;
    int ntile = (n + 127) / 128;

    k_init<<<(n + 255) / 256, 256>>>((const int*)ei, n);
    k_hist<<<(E / 2 + 255) / 256, 256>>>(ei, E, n);
    k_xconv<<<(n * 32 + 255) / 256, 256>>>(x, n);
    k_wconv<<<64, 256>>>(W1l, W1r, W2l, W2r);
    k_scanA<<<nb, 1024>>>(n);
    k_scanB<<<1, 1024>>>(nb);
    k_scanC<<<(n + 255) / 256, 256>>>(n, E);
    k_fill<<<(E / 2 + 255) / 256, 256>>>(E);

    // layer 1 (aggregation fused into GEMM)
    k_mma<<<ntile, 256, SMEM_MMA_BYTES>>>(0, b1, nullptr, n);

    // layer 2
    k_mma<<<ntile, 256, SMEM_MMA_BYTES>>>(1, b2, out, n);
    k_aggmean_add<<<(n * 32 + 255) / 256, 256>>>(out, n);
}